// round 16
// baseline (speedup 1.0000x reference)
#include <cuda_runtime.h>
#include <cuda_fp16.h>
#include <cstdint>

#define BATCH 16
#define CIN   256
#define COUT  256
#define HH    64
#define WW    64
#define LAT   512

// ---------------- scratch (device globals; no allocation) ----------------
__device__ __align__(16) float g_s[BATCH * CIN];
__device__ __align__(16) float g_d[BATCH * COUT];
__device__ __align__(16) float g_wss[CIN * COUT];
// fp16 A panels, fragment-major: [b][cot][c(24)][ks(6)][wm(2)][mt(4)][lane(32)] uint4
__device__ __align__(16) uint4 g_wA[(size_t)BATCH * 2 * 24 * 6 * 2 * 4 * 32];
// fp16 x, ci-pair packed: [b][ci2(128)][y(64)][x(64)] half2-as-uint
__device__ __align__(16) unsigned g_x16[(size_t)BATCH * 128 * HH * WW];

__device__ __forceinline__ unsigned h2u(__half2 h) {
    return *reinterpret_cast<unsigned*>(&h);
}

// ---------------- prep 1: style affine + wss + vectorized x->fp16 pack ----------------
__global__ void fused1_kernel(const float* __restrict__ style,
                              const float* __restrict__ style_w,
                              const float* __restrict__ style_b,
                              const float* __restrict__ weight,
                              const float* __restrict__ x) {
    if (blockIdx.x < 16) {
        __shared__ float st[LAT];
        int b = blockIdx.x, tid = threadIdx.x;
        st[tid]       = style[b * LAT + tid];
        st[tid + 256] = style[b * LAT + tid + 256];
        __syncthreads();
        float acc = style_b[tid];
#pragma unroll 8
        for (int l = 0; l < LAT; l++) acc += st[l] * style_w[l * CIN + tid];
        g_s[b * CIN + tid] = acc;
    } else if (blockIdx.x < 272) {
        int ci = blockIdx.x - 16, co = threadIdx.x;
        const float* wp = weight + co * (CIN * 9) + ci * 9;
        float s = 0.f;
#pragma unroll
        for (int t = 0; t < 9; t++) { float v = wp[t]; s += v * v; }
        g_wss[ci * COUT + co] = s;
    } else {
        // x-pack: 4 pixels/thread, 2x LDG.128 + 1x STG.128, fully coalesced
        int q = (blockIdx.x - 272) * 256 + threadIdx.x;  // 0 .. 16*128*1024-1
        int pix4 = q & 1023;
        int r    = q >> 10;            // b*128 + ci2
        int ci2  = r & 127;
        int b    = r >> 7;
        const float4* p0 = (const float4*)(x + (((size_t)(b * 256 + 2 * ci2)) << 12)) + pix4;
        float4 a = p0[0];
        float4 c = p0[1024];           // +4096 floats = next ci plane
        uint4 o;
        o.x = h2u(__floats2half2_rn(a.x, c.x));
        o.y = h2u(__floats2half2_rn(a.y, c.y));
        o.z = h2u(__floats2half2_rn(a.z, c.z));
        o.w = h2u(__floats2half2_rn(a.w, c.w));
        ((uint4*)g_x16)[q] = o;
    }
}

__global__ void d_kernel() {
    __shared__ float s2[CIN];
    int b = blockIdx.x, co = threadIdx.x;
    float sv = g_s[b * CIN + co];
    s2[co] = sv * sv;
    __syncthreads();
    float acc = 1e-8f;
#pragma unroll 8
    for (int ci = 0; ci < CIN; ci++) acc += g_wss[ci * COUT + co] * s2[ci];
    g_d[b * COUT + co] = rsqrtf(acc);
}

// ---------------- prep 2: fp16 fragment-major modulated weights ----------------
// Batch-paired: one set of 8 scattered weight reads serves batches b and b+8.
__global__ void wa_kernel(const float* __restrict__ weight) {
    int o = blockIdx.x * 256 + threadIdx.x;   // uint4 index for b in 0..7 (589824 total)
    int lane = o & 31; int t = o >> 5;
    int mt = t & 3;  t >>= 2;
    int wm = t & 1;  t >>= 1;
    int ks = t % 6;  t /= 6;
    int c  = t % 24; t /= 24;
    int cot = t & 1; int b = t >> 1;          // 0..7
    int g = lane >> 2, tig = lane & 3;
    int cig = c / 3;
    int tap = (c % 3) * 3 + (ks >> 1);
    int ci  = cig * 32 + (ks & 1) * 16 + 2 * tig;
    int co  = cot * 128 + wm * 64 + mt * 16 + g;
    // 8 scattered weight reads, shared across the batch pair
    float w00 = weight[(co * CIN + ci) * 9 + tap];
    float w01 = weight[(co * CIN + ci + 1) * 9 + tap];
    float w10 = weight[((co + 8) * CIN + ci) * 9 + tap];
    float w11 = weight[((co + 8) * CIN + ci + 1) * 9 + tap];
    float w20 = weight[(co * CIN + ci + 8) * 9 + tap];
    float w21 = weight[(co * CIN + ci + 9) * 9 + tap];
    float w30 = weight[((co + 8) * CIN + ci + 8) * 9 + tap];
    float w31 = weight[((co + 8) * CIN + ci + 9) * 9 + tap];
#pragma unroll
    for (int h = 0; h < 2; h++) {
        int bb = b + h * 8;
        float d0 = g_d[bb * COUT + co], d1 = g_d[bb * COUT + co + 8];
        float s0 = g_s[bb * CIN + ci],     s1 = g_s[bb * CIN + ci + 1];
        float s8 = g_s[bb * CIN + ci + 8], s9 = g_s[bb * CIN + ci + 9];
        uint4 r;
        r.x = h2u(__floats2half2_rn(w00 * s0 * d0, w01 * s1 * d0));
        r.y = h2u(__floats2half2_rn(w10 * s0 * d1, w11 * s1 * d1));
        r.z = h2u(__floats2half2_rn(w20 * s8 * d0, w21 * s9 * d0));
        r.w = h2u(__floats2half2_rn(w30 * s8 * d1, w31 * s9 * d1));
        g_wA[o + h * 589824] = r;
    }
}

// ---------------- main: fp16 m16n8k16, K=96 chunks, async pipeline (R14, unchanged) ----------------
#define A_STAGE    24576               // 1536 uint4
#define SLAB_U     296                 // 4B units per ci2; %32==8 -> conflict-free
#define SLAB_UNITS (16 * SLAB_U)       // 4736
#define SLAB_BYTES (SLAB_UNITS * 4)    // 18944
#define SMEM_BYTES (2 * A_STAGE + 2 * SLAB_BYTES)   // 87040 -> 2 CTAs/SM

#define CP16_CG(dst, src) \
    asm volatile("cp.async.cg.shared.global [%0], [%1], 16;" :: "r"(dst), "l"(src))
#define CP_COMMIT()   asm volatile("cp.async.commit_group;" ::: "memory")
#define CP_WAIT_ALL() asm volatile("cp.async.wait_group 0;" ::: "memory")

#define MMA_F16(c, a, b0, b1)                                                  \
    asm volatile("mma.sync.aligned.m16n8k16.row.col.f32.f16.f16.f32 "          \
        "{%0,%1,%2,%3}, {%4,%5,%6,%7}, {%8,%9}, {%0,%1,%2,%3};"                \
        : "+f"((c)[0]), "+f"((c)[1]), "+f"((c)[2]), "+f"((c)[3])               \
        : "r"((a).x), "r"((a).y), "r"((a).z), "r"((a).w), "r"(b0), "r"(b1))

__global__ void __launch_bounds__(256, 2)
conv_mma(const float* __restrict__ noise, const float* __restrict__ bias,
         const float* __restrict__ nwptr, float* __restrict__ out) {
    extern __shared__ __align__(16) char smem[];
    unsigned* slabu = (unsigned*)(smem + 2 * A_STAGE);
    const uint32_t sbase = (uint32_t)__cvta_generic_to_shared(smem);

    const int tid  = threadIdx.x;
    const int w    = tid >> 5;
    const int lane = tid & 31;
    const int g    = lane >> 2;
    const int tig  = lane & 3;
    const int wm   = w >> 2;
    const int wn   = w & 3;

    const int y0     = blockIdx.x * 2;
    const int coBase = blockIdx.y * 128;
    const int b      = blockIdx.z;

    const unsigned* x16b = g_x16 + (((size_t)b * 128) << 12);
    const uint4* wa4 = g_wA + ((size_t)(b * 2 + blockIdx.y)) * (24 * 1536);

    for (int i = tid; i < 2 * SLAB_UNITS / 4; i += 256)
        ((uint4*)slabu)[i] = make_uint4(0u, 0u, 0u, 0u);

    float c[4][4][4];
#pragma unroll
    for (int mt = 0; mt < 4; mt++)
#pragma unroll
        for (int nt = 0; nt < 4; nt++)
#pragma unroll
            for (int i = 0; i < 4; i++) c[mt][nt][i] = 0.f;

    auto load_A = [&](int ch, int buf) {
        const uint32_t abase = sbase + buf * A_STAGE;
        const uint4* src4 = wa4 + ch * 1536;
#pragma unroll
        for (int i = 0; i < 6; i++) {
            int idx = tid + 256 * i;
            CP16_CG(abase + idx * 16, src4 + idx);
        }
    };
    auto load_slab_piece = [&](int cig, int sb, int piece) {
        const uint32_t slbase = sbase + 2 * A_STAGE + sb * SLAB_BYTES;
        int o   = piece * 256 + tid;
        int row = o >> 4;
        int f   = o & 15;
        int ci2 = row >> 2;
        int ry  = row & 3;
        int y   = y0 - 1 + ry;
        if ((unsigned)y < HH) {
            const unsigned* src = x16b + (((size_t)(cig * 16 + ci2)) << 12) + y * WW + f * 4;
            CP16_CG(slbase + (ci2 * SLAB_U + ry * 68 + 4 + f * 4) * 4, src);
        }
    };

    __syncthreads();
    load_A(0, 0);
#pragma unroll
    for (int p = 0; p < 4; p++) load_slab_piece(0, 0, p);
    CP_COMMIT();
    CP_WAIT_ALL();
    __syncthreads();

    const int bfrag0 = tig * SLAB_U + (wn >> 1) * 68 + (wn & 1) * 32 + g + 3;

    for (int ch = 0; ch < 24; ch++) {
        if (ch > 0) { CP_WAIT_ALL(); __syncthreads(); }

        const int cig = ch / 3;
        const int j   = ch - 3 * cig;
        if (ch + 1 < 24) load_A(ch + 1, (ch + 1) & 1);
        if (cig + 1 < 8) {
            if (j == 0)      { load_slab_piece(cig + 1, (cig + 1) & 1, 0);
                               load_slab_piece(cig + 1, (cig + 1) & 1, 1); }
            else if (j == 1) { load_slab_piece(cig + 1, (cig + 1) & 1, 2);
                               load_slab_piece(cig + 1, (cig + 1) & 1, 3); }
        }
        CP_COMMIT();

        const unsigned* sl = slabu + (cig & 1) * SLAB_UNITS;
        const uint4* Af = (const uint4*)(smem + (ch & 1) * A_STAGE);
        const int tapBase = j * 3;

#pragma unroll
        for (int ks = 0; ks < 6; ks++) {
            uint4 a[4];
#pragma unroll
            for (int mt = 0; mt < 4; mt++)
                a[mt] = Af[((ks * 2 + wm) * 4 + mt) * 32 + lane];
            const int tap = tapBase + (ks >> 1);
            const int ky = tap / 3;
            const int kx = tap - ky * 3;
            const unsigned* bk = sl + bfrag0 + ky * 68 + kx + (ks & 1) * (8 * SLAB_U);
            unsigned b0[4], b1[4];
#pragma unroll
            for (int nt = 0; nt < 4; nt++) {
                b0[nt] = bk[nt * 8];
                b1[nt] = bk[nt * 8 + 4 * SLAB_U];
            }
#pragma unroll
            for (int mt = 0; mt < 4; mt++)
#pragma unroll
                for (int nt = 0; nt < 4; nt++)
                    MMA_F16(c[mt][nt], a[mt], b0[nt], b1[nt]);
        }
    }

    // ---- epilogue: noise + bias + leaky_relu * sqrt(2)
    {
        const float nw = nwptr[0];
        const int y = y0 + (wn >> 1);
        const float* nzrow = noise + (size_t)b * (HH * WW) + y * WW;
#pragma unroll
        for (int mt = 0; mt < 4; mt++) {
            int co0 = coBase + wm * 64 + mt * 16 + g;
            float bv0 = bias[co0];
            float bv1 = bias[co0 + 8];
            float* o0 = out + (size_t)(b * COUT + co0) * (HH * WW) + y * WW;
            float* o1 = o0 + 8 * (HH * WW);
#pragma unroll
            for (int nt = 0; nt < 4; nt++) {
                int xc = (wn & 1) * 32 + nt * 8 + tig * 2;
                float2 nz = *(const float2*)(nzrow + xc);
                float nzx = nz.x * nw, nzy = nz.y * nw;
                float v0 = c[mt][nt][0] + nzx + bv0;
                float v1 = c[mt][nt][1] + nzy + bv0;
                float v2 = c[mt][nt][2] + nzx + bv1;
                float v3 = c[mt][nt][3] + nzy + bv1;
                v0 = (v0 > 0.f ? v0 : 0.2f * v0) * 1.41421356237309515f;
                v1 = (v1 > 0.f ? v1 : 0.2f * v1) * 1.41421356237309515f;
                v2 = (v2 > 0.f ? v2 : 0.2f * v2) * 1.41421356237309515f;
                v3 = (v3 > 0.f ? v3 : 0.2f * v3) * 1.41421356237309515f;
                *(float2*)(o0 + xc) = make_float2(v0, v1);
                *(float2*)(o1 + xc) = make_float2(v2, v3);
            }
        }
    }
}

// ---------------- launch ----------------
extern "C" void kernel_launch(void* const* d_in, const int* in_sizes, int n_in,
                              void* d_out, int out_size) {
    const float* x        = (const float*)d_in[0];
    const float* style    = (const float*)d_in[1];
    const float* noise    = (const float*)d_in[2];
    const float* weight   = (const float*)d_in[3];
    const float* style_w  = (const float*)d_in[4];
    const float* style_b  = (const float*)d_in[5];
    const float* bias     = (const float*)d_in[6];
    const float* nw       = (const float*)d_in[7];
    float* out = (float*)d_out;

    cudaFuncSetAttribute(conv_mma, cudaFuncAttributeMaxDynamicSharedMemorySize, SMEM_BYTES);

    fused1_kernel<<<272 + 8192, 256>>>(style, style_w, style_b, weight, x);  // 1
    d_kernel<<<BATCH, 256>>>();                                              // 2
    wa_kernel<<<2304, 256>>>(weight);                                        // 3
    conv_mma<<<dim3(32, 2, 16), 256, SMEM_BYTES>>>(noise, bias, nw, out);    // 4
}

// round 17
// speedup vs baseline: 1.4362x; 1.4362x over previous
#include <cuda_runtime.h>
#include <cuda_fp16.h>
#include <cstdint>

#define BATCH 16
#define CIN   256
#define COUT  256
#define HH    64
#define WW    64
#define LAT   512

// ---------------- scratch (device globals; no allocation) ----------------
__device__ __align__(16) float g_s[BATCH * CIN];
__device__ __align__(16) float g_d[BATCH * COUT];
__device__ __align__(16) float g_wss[CIN * COUT];
// fp16 A panels, fragment-major: [b][cot][c(24)][ks(6)][wm(2)][mt(4)][lane(32)] uint4
__device__ __align__(16) uint4 g_wA[(size_t)BATCH * 2 * 24 * 6 * 2 * 4 * 32];
// fp16 x, ci-pair packed: [b][ci2(128)][y(64)][x(64)] half2-as-uint
__device__ __align__(16) unsigned g_x16[(size_t)BATCH * 128 * HH * WW];

__device__ __forceinline__ unsigned h2u(__half2 h) {
    return *reinterpret_cast<unsigned*>(&h);
}

// ---------------- prep 1: style affine + wss + vectorized x->fp16 pack ----------------
__global__ void fused1_kernel(const float* __restrict__ style,
                              const float* __restrict__ style_w,
                              const float* __restrict__ style_b,
                              const float* __restrict__ weight,
                              const float* __restrict__ x) {
    if (blockIdx.x < 16) {
        __shared__ float st[LAT];
        int b = blockIdx.x, tid = threadIdx.x;
        st[tid]       = style[b * LAT + tid];
        st[tid + 256] = style[b * LAT + tid + 256];
        __syncthreads();
        float acc = style_b[tid];
#pragma unroll 8
        for (int l = 0; l < LAT; l++) acc += st[l] * style_w[l * CIN + tid];
        g_s[b * CIN + tid] = acc;
    } else if (blockIdx.x < 272) {
        int ci = blockIdx.x - 16, co = threadIdx.x;
        const float* wp = weight + co * (CIN * 9) + ci * 9;
        float s = 0.f;
#pragma unroll
        for (int t = 0; t < 9; t++) { float v = wp[t]; s += v * v; }
        g_wss[ci * COUT + co] = s;
    } else {
        // x-pack: 4 pixels/thread, 2x LDG.128 + 1x STG.128, fully coalesced
        int q = (blockIdx.x - 272) * 256 + threadIdx.x;  // 0 .. 16*128*1024-1
        int pix4 = q & 1023;
        int r    = q >> 10;            // b*128 + ci2
        int ci2  = r & 127;
        int b    = r >> 7;
        const float4* p0 = (const float4*)(x + (((size_t)(b * 256 + 2 * ci2)) << 12)) + pix4;
        float4 a = p0[0];
        float4 c = p0[1024];           // +4096 floats = next ci plane
        uint4 o;
        o.x = h2u(__floats2half2_rn(a.x, c.x));
        o.y = h2u(__floats2half2_rn(a.y, c.y));
        o.z = h2u(__floats2half2_rn(a.z, c.z));
        o.w = h2u(__floats2half2_rn(a.w, c.w));
        ((uint4*)g_x16)[q] = o;
    }
}

__global__ void d_kernel() {
    __shared__ float s2[CIN];
    int b = blockIdx.x, co = threadIdx.x;
    float sv = g_s[b * CIN + co];
    s2[co] = sv * sv;
    __syncthreads();
    float acc = 1e-8f;
#pragma unroll 8
    for (int ci = 0; ci < CIN; ci++) acc += g_wss[ci * COUT + co] * s2[ci];
    g_d[b * COUT + co] = rsqrtf(acc);
}

// ---------------- prep 2: fp16 fragment-major modulated weights ----------------
// Batch-paired: one set of 8 scattered weight reads serves batches b and b+8.
__global__ void wa_kernel(const float* __restrict__ weight) {
    int o = blockIdx.x * 256 + threadIdx.x;   // uint4 index for b in 0..7 (589824 total)
    int lane = o & 31; int t = o >> 5;
    int mt = t & 3;  t >>= 2;
    int wm = t & 1;  t >>= 1;
    int ks = t % 6;  t /= 6;
    int c  = t % 24; t /= 24;
    int cot = t & 1; int b = t >> 1;          // 0..7
    int g = lane >> 2, tig = lane & 3;
    int cig = c / 3;
    int tap = (c % 3) * 3 + (ks >> 1);
    int ci  = cig * 32 + (ks & 1) * 16 + 2 * tig;
    int co  = cot * 128 + wm * 64 + mt * 16 + g;
    // 8 scattered weight reads, shared across the batch pair
    float w00 = weight[(co * CIN + ci) * 9 + tap];
    float w01 = weight[(co * CIN + ci + 1) * 9 + tap];
    float w10 = weight[((co + 8) * CIN + ci) * 9 + tap];
    float w11 = weight[((co + 8) * CIN + ci + 1) * 9 + tap];
    float w20 = weight[(co * CIN + ci + 8) * 9 + tap];
    float w21 = weight[(co * CIN + ci + 9) * 9 + tap];
    float w30 = weight[((co + 8) * CIN + ci + 8) * 9 + tap];
    float w31 = weight[((co + 8) * CIN + ci + 9) * 9 + tap];
#pragma unroll
    for (int h = 0; h < 2; h++) {
        int bb = b + h * 8;
        float d0 = g_d[bb * COUT + co], d1 = g_d[bb * COUT + co + 8];
        float s0 = g_s[bb * CIN + ci],     s1 = g_s[bb * CIN + ci + 1];
        float s8 = g_s[bb * CIN + ci + 8], s9 = g_s[bb * CIN + ci + 9];
        uint4 r;
        r.x = h2u(__floats2half2_rn(w00 * s0 * d0, w01 * s1 * d0));
        r.y = h2u(__floats2half2_rn(w10 * s0 * d1, w11 * s1 * d1));
        r.z = h2u(__floats2half2_rn(w20 * s8 * d0, w21 * s9 * d0));
        r.w = h2u(__floats2half2_rn(w30 * s8 * d1, w31 * s9 * d1));
        g_wA[o + h * 589824] = r;
    }
}

// ---------------- main: fp16 m16n8k16, K=96 chunks, async pipeline ----------------
#define A_STAGE    24576               // 1536 uint4
#define SLAB_U     296                 // 4B units per ci2; %32==8 -> conflict-free
#define SLAB_UNITS (16 * SLAB_U)       // 4736
#define SLAB_BYTES (SLAB_UNITS * 4)    // 18944
#define SMEM_BYTES (2 * A_STAGE + 2 * SLAB_BYTES)   // 87040 -> 2 CTAs/SM

#define CP16_CG(dst, src) \
    asm volatile("cp.async.cg.shared.global [%0], [%1], 16;" :: "r"(dst), "l"(src))
#define CP_COMMIT()   asm volatile("cp.async.commit_group;" ::: "memory")
#define CP_WAIT_ALL() asm volatile("cp.async.wait_group 0;" ::: "memory")

#define MMA_F16(c, a, b0, b1)                                                  \
    asm volatile("mma.sync.aligned.m16n8k16.row.col.f32.f16.f16.f32 "          \
        "{%0,%1,%2,%3}, {%4,%5,%6,%7}, {%8,%9}, {%0,%1,%2,%3};"                \
        : "+f"((c)[0]), "+f"((c)[1]), "+f"((c)[2]), "+f"((c)[3])               \
        : "r"((a).x), "r"((a).y), "r"((a).z), "r"((a).w), "r"(b0), "r"(b1))

__global__ void __launch_bounds__(256, 2)
conv_mma(const float* __restrict__ noise, const float* __restrict__ bias,
         const float* __restrict__ nwptr, float* __restrict__ out) {
    extern __shared__ __align__(16) char smem[];
    unsigned* slabu = (unsigned*)(smem + 2 * A_STAGE);
    const uint32_t sbase = (uint32_t)__cvta_generic_to_shared(smem);

    const int tid  = threadIdx.x;
    const int w    = tid >> 5;
    const int lane = tid & 31;
    const int g    = lane >> 2;
    const int tig  = lane & 3;
    const int wm   = w >> 2;
    const int wn   = w & 3;

    const int y0     = blockIdx.x * 2;
    const int coBase = blockIdx.y * 128;
    const int b      = blockIdx.z;

    const unsigned* x16b = g_x16 + (((size_t)b * 128) << 12);
    const uint4* wa4 = g_wA + ((size_t)(b * 2 + blockIdx.y)) * (24 * 1536);

    for (int i = tid; i < 2 * SLAB_UNITS / 4; i += 256)
        ((uint4*)slabu)[i] = make_uint4(0u, 0u, 0u, 0u);

    float c[4][4][4];
#pragma unroll
    for (int mt = 0; mt < 4; mt++)
#pragma unroll
        for (int nt = 0; nt < 4; nt++)
#pragma unroll
            for (int i = 0; i < 4; i++) c[mt][nt][i] = 0.f;

    auto load_A = [&](int ch, int buf) {
        const uint32_t abase = sbase + buf * A_STAGE;
        const uint4* src4 = wa4 + ch * 1536;
#pragma unroll
        for (int i = 0; i < 6; i++) {
            int idx = tid + 256 * i;
            CP16_CG(abase + idx * 16, src4 + idx);
        }
    };
    auto load_slab_piece = [&](int cig, int sb, int piece) {
        const uint32_t slbase = sbase + 2 * A_STAGE + sb * SLAB_BYTES;
        int o   = piece * 256 + tid;
        int row = o >> 4;
        int f   = o & 15;
        int ci2 = row >> 2;
        int ry  = row & 3;
        int y   = y0 - 1 + ry;
        if ((unsigned)y < HH) {
            const unsigned* src = x16b + (((size_t)(cig * 16 + ci2)) << 12) + y * WW + f * 4;
            CP16_CG(slbase + (ci2 * SLAB_U + ry * 68 + 4 + f * 4) * 4, src);
        }
    };

    __syncthreads();
    load_A(0, 0);
#pragma unroll
    for (int p = 0; p < 4; p++) load_slab_piece(0, 0, p);
    CP_COMMIT();
    CP_WAIT_ALL();
    __syncthreads();

    const int bfrag0 = tig * SLAB_U + (wn >> 1) * 68 + (wn & 1) * 32 + g + 3;

    for (int ch = 0; ch < 24; ch++) {
        if (ch > 0) { CP_WAIT_ALL(); __syncthreads(); }

        const int cig = ch / 3;
        const int j   = ch - 3 * cig;
        if (ch + 1 < 24) load_A(ch + 1, (ch + 1) & 1);
        if (cig + 1 < 8) {
            if (j == 0)      { load_slab_piece(cig + 1, (cig + 1) & 1, 0);
                               load_slab_piece(cig + 1, (cig + 1) & 1, 1); }
            else if (j == 1) { load_slab_piece(cig + 1, (cig + 1) & 1, 2);
                               load_slab_piece(cig + 1, (cig + 1) & 1, 3); }
        }
        CP_COMMIT();

        const unsigned* sl = slabu + (cig & 1) * SLAB_UNITS;
        const uint4* Af = (const uint4*)(smem + (ch & 1) * A_STAGE);
        const int tapBase = j * 3;

#pragma unroll
        for (int ks = 0; ks < 6; ks++) {
            uint4 a[4];
#pragma unroll
            for (int mt = 0; mt < 4; mt++)
                a[mt] = Af[((ks * 2 + wm) * 4 + mt) * 32 + lane];
            const int tap = tapBase + (ks >> 1);
            const int ky = tap / 3;
            const int kx = tap - ky * 3;
            const unsigned* bk = sl + bfrag0 + ky * 68 + kx + (ks & 1) * (8 * SLAB_U);
            unsigned b0[4], b1[4];
#pragma unroll
            for (int nt = 0; nt < 4; nt++) {
                b0[nt] = bk[nt * 8];
                b1[nt] = bk[nt * 8 + 4 * SLAB_U];
            }
#pragma unroll
            for (int mt = 0; mt < 4; mt++)
#pragma unroll
                for (int nt = 0; nt < 4; nt++)
                    MMA_F16(c[mt][nt], a[mt], b0[nt], b1[nt]);
        }
    }

    // ---- epilogue: noise + bias + leaky_relu * sqrt(2)
    {
        const float nw = nwptr[0];
        const int y = y0 + (wn >> 1);
        const float* nzrow = noise + (size_t)b * (HH * WW) + y * WW;
#pragma unroll
        for (int mt = 0; mt < 4; mt++) {
            int co0 = coBase + wm * 64 + mt * 16 + g;
            float bv0 = bias[co0];
            float bv1 = bias[co0 + 8];
            float* o0 = out + (size_t)(b * COUT + co0) * (HH * WW) + y * WW;
            float* o1 = o0 + 8 * (HH * WW);
#pragma unroll
            for (int nt = 0; nt < 4; nt++) {
                int xc = (wn & 1) * 32 + nt * 8 + tig * 2;
                float2 nz = *(const float2*)(nzrow + xc);
                float nzx = nz.x * nw, nzy = nz.y * nw;
                float v0 = c[mt][nt][0] + nzx + bv0;
                float v1 = c[mt][nt][1] + nzy + bv0;
                float v2 = c[mt][nt][2] + nzx + bv1;
                float v3 = c[mt][nt][3] + nzy + bv1;
                v0 = (v0 > 0.f ? v0 : 0.2f * v0) * 1.41421356237309515f;
                v1 = (v1 > 0.f ? v1 : 0.2f * v1) * 1.41421356237309515f;
                v2 = (v2 > 0.f ? v2 : 0.2f * v2) * 1.41421356237309515f;
                v3 = (v3 > 0.f ? v3 : 0.2f * v3) * 1.41421356237309515f;
                *(float2*)(o0 + xc) = make_float2(v0, v1);
                *(float2*)(o1 + xc) = make_float2(v2, v3);
            }
        }
    }
}

// ---------------- launch ----------------
extern "C" void kernel_launch(void* const* d_in, const int* in_sizes, int n_in,
                              void* d_out, int out_size) {
    const float* x        = (const float*)d_in[0];
    const float* style    = (const float*)d_in[1];
    const float* noise    = (const float*)d_in[2];
    const float* weight   = (const float*)d_in[3];
    const float* style_w  = (const float*)d_in[4];
    const float* style_b  = (const float*)d_in[5];
    const float* bias     = (const float*)d_in[6];
    const float* nw       = (const float*)d_in[7];
    float* out = (float*)d_out;

    cudaFuncSetAttribute(conv_mma, cudaFuncAttributeMaxDynamicSharedMemorySize, SMEM_BYTES);

    fused1_kernel<<<272 + 8192, 256>>>(style, style_w, style_b, weight, x);  // 1
    d_kernel<<<BATCH, 256>>>();                                              // 2
    wa_kernel<<<2304, 256>>>(weight);                                        // 3
    conv_mma<<<dim3(32, 2, 16), 256, SMEM_BYTES>>>(noise, bias, nw, out);    // 4
}